// round 15
// baseline (speedup 1.0000x reference)
#include <cuda_runtime.h>
#include <cuda_fp16.h>
#include <math.h>
#include <stdint.h>

#define Nn 65536
#define Dd 1024
#define Ss 512
#define Kslots 64
#define AGG_BLOCKS 256
#define AGG_ROWS (Nn / AGG_BLOCKS)

// ======================= helpers =============================================
__device__ __forceinline__ uint32_t smem_u32(const void* p) {
    uint32_t a;
    asm("{ .reg .u64 t; cvta.to.shared.u64 t, %1; cvt.u32.u64 %0, t; }" : "=r"(a) : "l"(p));
    return a;
}
__device__ __forceinline__ void cp16(uint32_t dst, const void* src) {
    asm volatile("cp.async.cg.shared.global [%0], [%1], 16;" :: "r"(dst), "l"(src));
}
__device__ __forceinline__ void ldsm4(uint32_t* r, uint32_t addr) {
    asm volatile("ldmatrix.sync.aligned.m8n8.x4.shared.b16 {%0,%1,%2,%3}, [%4];"
                 : "=r"(r[0]), "=r"(r[1]), "=r"(r[2]), "=r"(r[3]) : "r"(addr));
}
__device__ __forceinline__ void hmma16(float* c, const uint32_t* a, const uint32_t* b) {
    asm volatile(
        "mma.sync.aligned.m16n8k16.row.col.f32.f16.f16.f32 "
        "{%0,%1,%2,%3}, {%4,%5,%6,%7}, {%8,%9}, {%0,%1,%2,%3};"
        : "+f"(c[0]), "+f"(c[1]), "+f"(c[2]), "+f"(c[3])
        : "r"(a[0]), "r"(a[1]), "r"(a[2]), "r"(a[3]), "r"(b[0]), "r"(b[1]));
}

// ======================= device global scratch ===============================
__device__ __align__(1024) __half g_ath[(size_t)Nn * Kslots];
__device__ __align__(1024) __half g_hh[(size_t)Nn * Dd];
__device__ __align__(1024) __half g_roh[(size_t)Nn * Dd];
__device__ __align__(1024) __half g_ersh[(size_t)Nn * Ss];
__device__ __align__(1024) __half g_cnth[(size_t)Nn * Ss];
__device__ __align__(1024) float g_weighted[(size_t)Nn * Kslots];
__device__ float g_gate[Nn];
__device__ __align__(1024) float g_partE[(size_t)AGG_BLOCKS * Kslots * Ss];
__device__ __align__(1024) float g_partW[(size_t)AGG_BLOCKS * Kslots * Ss];
// folded small matrices (fp16, hgemm-B layout [rows][K] K-major)
__device__ __align__(1024) __half g_m1T[(size_t)Kslots * Dd];
__device__ __align__(1024) __half g_m2T[(size_t)Kslots * Dd];
__device__ __align__(1024) __half g_vwoT[(size_t)Dd * Kslots];
__device__ __align__(1024) __half g_wall[(size_t)(2 * Ss) * Dd];
// fp32 precompute intermediates
__device__ __align__(1024) float g_Kp32[Kslots * Ss];
__device__ __align__(1024) float g_V32[Kslots * Ss];
__device__ __align__(1024) float g_WoT32[(size_t)Dd * Ss];

// ======================= fp16 GEMM (mma.sync, 3-stage pipeline) ==============
// C[M,Nc] = act( A @ B^T );  A [M,Kd] (fp16, or fp32 if A32), B [Nc,Kd] fp16.
// MODE 6: Nc=1024 fused: [0,512) sigmoid+bias -> Chi, [512,1024) tanh+bias2 -> Clo (fp16).
// MODE 7: Nc=64, fused row-softmax. SOFT=1: fp16 attn -> Chi. SOFT=2: fp32 softmax*gate -> Cf.
// MODE 8: fp16 out -> Chi.
template <int BM, int BN, int MODE, int SOFT, bool A32>
__global__ void __launch_bounds__(256, 2)
hgemm(const __half* __restrict__ Ah,
      const float* __restrict__ Af,
      const __half* __restrict__ B,
      int Kd, int Nc,
      float* __restrict__ Cf,
      __half* __restrict__ Chi, __half* __restrict__ Clo,
      const float* __restrict__ bias, const float* __restrict__ bias2,
      const float* __restrict__ gatep)
{
    constexpr int NWN = (BN >= 128) ? 4 : 2;
    constexpr int NWM = 8 / NWN;
    constexpr int WM = BM / NWM;
    constexpr int MF = WM / 16;
    constexpr int NF = (BN / NWN) / 8;
    constexpr int APL = BM * 128;
    constexpr int BPL = BN * 128;
    constexpr int STAGE = APL + BPL;
    constexpr int SEGS = (BM + BN) * 8;
    constexpr int SPT = SEGS / 256;
    constexpr int SPT_A = (BM * 8) / 256;
    constexpr int SPT_B = (BN * 8) / 256;

    extern __shared__ char smem_raw[];
    uint32_t sb0 = smem_u32(smem_raw);

    int tid = threadIdx.x, w = tid >> 5, lane = tid & 31;
    int row0 = blockIdx.y * BM, col0 = blockIdx.x * BN;
    int wm0 = (w / NWN) * WM, wn0 = (w % NWN) * (BN / NWN);
    int nch = Kd >> 6;

    float acc[MF][NF][4];
#pragma unroll
    for (int i = 0; i < MF; i++)
#pragma unroll
        for (int j = 0; j < NF; j++)
#pragma unroll
            for (int u = 0; u < 4; u++) acc[i][j][u] = 0.f;

    auto issue = [&](int c) {
        uint32_t sbase = sb0 + (c % 3) * STAGE;
        int k0 = c << 6;
        if (A32) {
#pragma unroll
            for (int i = 0; i < SPT_A; i++) {
                int sg = i * 256 + tid;
                int lr = sg >> 3, q = sg & 7;
                const float4* src = reinterpret_cast<const float4*>(
                    Af + (size_t)(row0 + lr) * Kd + k0 + q * 8);
                float4 v0 = src[0], v1 = src[1];
                __half2 h0 = __floats2half2_rn(v0.x, v0.y);
                __half2 h1 = __floats2half2_rn(v0.z, v0.w);
                __half2 h2 = __floats2half2_rn(v1.x, v1.y);
                __half2 h3 = __floats2half2_rn(v1.z, v1.w);
                uint32_t off = (uint32_t)(lr * 128 + q * 16);
                off ^= (off >> 3) & 0x70;
                uint4 pk;
                pk.x = *reinterpret_cast<uint32_t*>(&h0);
                pk.y = *reinterpret_cast<uint32_t*>(&h1);
                pk.z = *reinterpret_cast<uint32_t*>(&h2);
                pk.w = *reinterpret_cast<uint32_t*>(&h3);
                *reinterpret_cast<uint4*>(smem_raw + ((c % 3) * STAGE + off)) = pk;
            }
#pragma unroll
            for (int i = 0; i < SPT_B; i++) {
                int sg = i * 256 + tid;
                int lr = sg >> 3, q = sg & 7;
                const __half* srcp = B + (size_t)(col0 + lr) * Kd + k0 + q * 8;
                uint32_t off = (uint32_t)(lr * 128 + q * 16);
                off ^= (off >> 3) & 0x70;
                cp16(sbase + APL + off, (const void*)srcp);
            }
        } else {
#pragma unroll
            for (int i = 0; i < SPT; i++) {
                int sg = i * 256 + tid;
                int rr = sg >> 3, q = sg & 7;
                const __half* srcp;
                uint32_t dstb;
                int lr;
                if (rr < BM) {
                    lr = rr;
                    srcp = Ah + (size_t)(row0 + lr) * Kd + k0 + q * 8;
                    dstb = sbase;
                } else {
                    lr = rr - BM;
                    srcp = B + (size_t)(col0 + lr) * Kd + k0 + q * 8;
                    dstb = sbase + APL;
                }
                uint32_t off = (uint32_t)(lr * 128 + q * 16);
                off ^= (off >> 3) & 0x70;
                cp16(dstb + off, (const void*)srcp);
            }
        }
        asm volatile("cp.async.commit_group;");
    };

    issue(0);
    if (nch > 1) issue(1);
    for (int c = 0; c < nch; c++) {
        if (c + 2 < nch) {
            issue(c + 2);
            asm volatile("cp.async.wait_group 2;");
        } else if (c + 1 < nch) {
            asm volatile("cp.async.wait_group 1;");
        } else {
            asm volatile("cp.async.wait_group 0;");
        }
        __syncthreads();

        uint32_t sA = sb0 + (c % 3) * STAGE;
        uint32_t sB = sA + APL;
#pragma unroll
        for (int ks = 0; ks < 4; ks++) {
            uint32_t ah[MF][4];
#pragma unroll
            for (int i = 0; i < MF; i++) {
                uint32_t off = (uint32_t)((wm0 + i * 16 + (lane & 15)) * 128 +
                                          ks * 32 + ((lane >> 4) << 4));
                off ^= (off >> 3) & 0x70;
                ldsm4(ah[i], sA + off);
            }
            uint32_t b[NF][2];
#pragma unroll
            for (int j2 = 0; j2 < NF / 2; j2++) {
                uint32_t off = (uint32_t)((wn0 + j2 * 16 + (lane & 7) + ((lane >> 4) << 3)) * 128 +
                                          ks * 32 + (((lane >> 3) & 1) << 4));
                off ^= (off >> 3) & 0x70;
                uint32_t t[4];
                ldsm4(t, sB + off);
                b[2 * j2][0] = t[0]; b[2 * j2][1] = t[1];
                b[2 * j2 + 1][0] = t[2]; b[2 * j2 + 1][1] = t[3];
            }
#pragma unroll
            for (int i = 0; i < MF; i++)
#pragma unroll
                for (int j = 0; j < NF; j++) hmma16(acc[i][j], ah[i], b[j]);
        }
        __syncthreads();
    }

    // ---- epilogue ----
    if (MODE == 7) {
        constexpr int RPW = BM / 8;   // rows per warp in softmax pass
        float* Sf = reinterpret_cast<float*>(smem_raw);
#pragma unroll
        for (int i = 0; i < MF; i++)
#pragma unroll
            for (int j = 0; j < NF; j++) {
                int rl = wm0 + i * 16 + (lane >> 2);
                int cl = wn0 + j * 8 + ((lane & 3) << 1);
#pragma unroll
                for (int half = 0; half < 2; half++) {
                    Sf[(rl + half * 8) * 68 + cl]     = acc[i][j][half * 2 + 0];
                    Sf[(rl + half * 8) * 68 + cl + 1] = acc[i][j][half * 2 + 1];
                }
            }
        __syncthreads();
#pragma unroll 1
        for (int r2 = 0; r2 < RPW; r2++) {
            int rl = w * RPW + r2;
            float v0 = Sf[rl * 68 + lane];
            float v1 = Sf[rl * 68 + 32 + lane];
            float m = fmaxf(v0, v1);
#pragma unroll
            for (int o = 16; o; o >>= 1) m = fmaxf(m, __shfl_xor_sync(0xffffffffu, m, o));
            float e0 = __expf(v0 - m), e1 = __expf(v1 - m);
            float s = e0 + e1;
#pragma unroll
            for (int o = 16; o; o >>= 1) s += __shfl_xor_sync(0xffffffffu, s, o);
            float inv = 1.f / s;
            size_t grow = (size_t)(row0 + rl);
            if (SOFT == 2) inv *= gatep[grow];
            float a0 = e0 * inv, a1 = e1 * inv;
            if (SOFT == 1) {
                Chi[grow * 64 + lane] = __float2half(a0);
                Chi[grow * 64 + 32 + lane] = __float2half(a1);
            } else {
                Cf[grow * 64 + lane] = a0;
                Cf[grow * 64 + 32 + lane] = a1;
            }
        }
        return;
    }

    int seg = col0 >> 9;   // MODE 6
#pragma unroll
    for (int i = 0; i < MF; i++) {
#pragma unroll
        for (int j = 0; j < NF; j++) {
            int r = row0 + wm0 + i * 16 + (lane >> 2);
            int cp = col0 + wn0 + j * 8 + ((lane & 3) << 1);
#pragma unroll
            for (int half = 0; half < 2; half++) {
                int rr = r + half * 8;
                float x0 = acc[i][j][half * 2 + 0];
                float x1 = acc[i][j][half * 2 + 1];
                if (MODE == 6) {
                    int colL = cp - seg * 512;
                    __half2 o;
                    if (seg == 0) {
                        o.x = __float2half(1.f / (1.f + __expf(-(x0 + bias[colL]))));
                        o.y = __float2half(1.f / (1.f + __expf(-(x1 + bias[colL + 1]))));
                        *reinterpret_cast<__half2*>(&Chi[(size_t)rr * Ss + colL]) = o;
                    } else {
                        o.x = __float2half(tanhf(x0 + bias2[colL]));
                        o.y = __float2half(tanhf(x1 + bias2[colL + 1]));
                        *reinterpret_cast<__half2*>(&Clo[(size_t)rr * Ss + colL]) = o;
                    }
                } else {  // MODE 8
                    __half2 o;
                    o.x = __float2half(x0);
                    o.y = __float2half(x1);
                    *reinterpret_cast<__half2*>(&Chi[(size_t)rr * Nc + cp]) = o;
                }
            }
        }
    }
}

// ======================= prep / elementwise kernels ==========================
__global__ void transpose_h_kernel(const float* __restrict__ W,
                                   __half* __restrict__ T, int R, int C) {
    __shared__ float t[32][33];
    int c0 = blockIdx.x * 32, r0 = blockIdx.y * 32;
    int tx = threadIdx.x, ty = threadIdx.y;
#pragma unroll
    for (int i = 0; i < 32; i += 8)
        t[ty + i][tx] = W[(size_t)(r0 + ty + i) * C + c0 + tx];
    __syncthreads();
#pragma unroll
    for (int i = 0; i < 32; i += 8)
        T[(size_t)(c0 + ty + i) * R + r0 + tx] = __float2half(t[tx][ty + i]);
}

__global__ void transpose_f_kernel(const float* __restrict__ W,
                                   float* __restrict__ T, int R, int C) {
    __shared__ float t[32][33];
    int c0 = blockIdx.x * 32, r0 = blockIdx.y * 32;
    int tx = threadIdx.x, ty = threadIdx.y;
#pragma unroll
    for (int i = 0; i < 32; i += 8)
        t[ty + i][tx] = W[(size_t)(r0 + ty + i) * C + c0 + tx];
    __syncthreads();
#pragma unroll
    for (int i = 0; i < 32; i += 8)
        T[(size_t)(c0 + ty + i) * R + r0 + tx] = t[tx][ty + i];
}

__global__ void __launch_bounds__(512)
kv2_kernel(const float* __restrict__ state,
           const float* __restrict__ Wk,
           const float* __restrict__ Wv) {
    int j = blockIdx.x;
    int c = threadIdx.x;
    __shared__ float srow[Ss];
    srow[c] = state[j * Ss + c];
    __syncthreads();
    float ak = 0.f, av = 0.f;
#pragma unroll 8
    for (int t = 0; t < Ss; t++) {
        float s = srow[t];
        ak += s * Wk[t * Ss + c];
        av += s * Wv[t * Ss + c];
    }
    g_Kp32[j * Ss + c] = ak;
    g_V32[j * Ss + c] = av;
}

template <bool JD>
__global__ void __launch_bounds__(256)
fold_kernel(const float* __restrict__ A, const float* __restrict__ B,
            __half* __restrict__ out, float scale) {
    int w = (blockIdx.x * 256 + threadIdx.x) >> 5;
    int lane = threadIdx.x & 31;
    int j = w & 63, d = w >> 6;
    const float* ar = A + (size_t)d * Ss;
    const float* br = B + (size_t)j * Ss;
    float acc = 0.f;
#pragma unroll
    for (int i = 0; i < 16; i++)
        acc += ar[lane + 32 * i] * br[lane + 32 * i];
#pragma unroll
    for (int o = 16; o; o >>= 1) acc += __shfl_xor_sync(0xffffffffu, acc, o);
    if (lane == 0) {
        size_t idx = JD ? (size_t)j * Dd + d : (size_t)d * 64 + j;
        out[idx] = __float2half(acc * scale);
    }
}

__global__ void ln_gate_kernel(const float* __restrict__ nf,
                               const __half* __restrict__ roh,
                               const float* __restrict__ gamma,
                               const float* __restrict__ beta,
                               const float* __restrict__ Wg,
                               const float* __restrict__ bg,
                               float* __restrict__ h,
                               __half* __restrict__ hh,
                               float* __restrict__ gate) {
    int row = blockIdx.x;
    int tid = threadIdx.x;
    __shared__ float sh[16];
    float4 a = reinterpret_cast<const float4*>(nf + (size_t)row * Dd)[tid];
    __half2 r0 = reinterpret_cast<const __half2*>(roh + (size_t)row * Dd)[tid * 2];
    __half2 r1 = reinterpret_cast<const __half2*>(roh + (size_t)row * Dd)[tid * 2 + 1];
    float v0 = a.x + __half2float(r0.x), v1 = a.y + __half2float(r0.y);
    float v2 = a.z + __half2float(r1.x), v3 = a.w + __half2float(r1.y);
    float s = v0 + v1 + v2 + v3;
    float sq = v0 * v0 + v1 * v1 + v2 * v2 + v3 * v3;
    int lane = tid & 31, wid = tid >> 5;
#pragma unroll
    for (int o = 16; o; o >>= 1) {
        s += __shfl_xor_sync(0xffffffffu, s, o);
        sq += __shfl_xor_sync(0xffffffffu, sq, o);
    }
    if (lane == 0) { sh[wid] = s; sh[8 + wid] = sq; }
    __syncthreads();
    if (tid < 32) {
        float rs = (lane < 8) ? sh[lane] : 0.f;
        float rq = (lane < 8) ? sh[8 + lane] : 0.f;
#pragma unroll
        for (int o = 4; o; o >>= 1) {
            rs += __shfl_xor_sync(0xffffffffu, rs, o);
            rq += __shfl_xor_sync(0xffffffffu, rq, o);
        }
        if (lane == 0) { sh[0] = rs; sh[1] = rq; }
    }
    __syncthreads();
    float mu = sh[0] * (1.f / Dd);
    float var = sh[1] * (1.f / Dd) - mu * mu;
    float inv = rsqrtf(var + 1e-6f);
    __syncthreads();

    float4 g4 = reinterpret_cast<const float4*>(gamma)[tid];
    float4 b4 = reinterpret_cast<const float4*>(beta)[tid];
    float h0 = (v0 - mu) * inv * g4.x + b4.x;
    float h1 = (v1 - mu) * inv * g4.y + b4.y;
    float h2 = (v2 - mu) * inv * g4.z + b4.z;
    float h3 = (v3 - mu) * inv * g4.w + b4.w;
    float4 o4; o4.x = h0; o4.y = h1; o4.z = h2; o4.w = h3;
    reinterpret_cast<float4*>(h + (size_t)row * Dd)[tid] = o4;

    __half2 p0, p1;
    p0.x = __float2half(h0); p0.y = __float2half(h1);
    p1.x = __float2half(h2); p1.y = __float2half(h3);
    reinterpret_cast<__half2*>(hh + (size_t)row * Dd)[tid * 2] = p0;
    reinterpret_cast<__half2*>(hh + (size_t)row * Dd)[tid * 2 + 1] = p1;

    float4 w4 = reinterpret_cast<const float4*>(Wg)[tid];
    float gd = h0 * w4.x + h1 * w4.y + h2 * w4.z + h3 * w4.w;
#pragma unroll
    for (int o = 16; o; o >>= 1) gd += __shfl_xor_sync(0xffffffffu, gd, o);
    if (lane == 0) sh[wid] = gd;
    __syncthreads();
    if (tid == 0) {
        float t = 0.f;
#pragma unroll
        for (int wv = 0; wv < 8; wv++) t += sh[wv];
        gate[row] = 1.f / (1.f + __expf(-(t + bg[0])));
    }
}

// aggregate with 4-deep cp.async row pipeline:
// part[blk] = sum_{rows in chunk} w[row]^T (outer) vec[row]
__global__ void __launch_bounds__(512)
aggregate_kernel(const float* __restrict__ w, const __half* __restrict__ vec,
                 float* __restrict__ part) {
    int blk = blockIdx.x;
    int tid = threadIdx.x;
    int j = tid >> 3;
    int sb = tid & 7;
    float acc[64];
#pragma unroll
    for (int t = 0; t < 64; t++) acc[t] = 0.f;
    __shared__ __align__(16) float ws[4][64];
    __shared__ __align__(16) __half vs[4][Ss];
    int r0 = blk * AGG_ROWS;

    auto issue = [&](int r) {
        int s = r & 3;
        size_t row = (size_t)(r0 + r);
        if (tid < 16) {
            cp16(smem_u32(&ws[s][0]) + tid * 16, (const void*)(w + row * 64 + tid * 4));
        } else if (tid < 80) {
            int seg = tid - 16;
            cp16(smem_u32(&vs[s][0]) + seg * 16, (const void*)(vec + row * Ss + seg * 8));
        }
        asm volatile("cp.async.commit_group;");
    };

    issue(0); issue(1); issue(2);
    for (int r = 0; r < AGG_ROWS; r++) {
        int s = r & 3;
        if (r + 4 <= AGG_ROWS) {
            if (r + 3 < AGG_ROWS) issue(r + 3);
            if (r + 3 < AGG_ROWS) { asm volatile("cp.async.wait_group 3;"); }
            else                  { asm volatile("cp.async.wait_group 2;"); }
        } else if (r + 3 == AGG_ROWS) {
            asm volatile("cp.async.wait_group 2;");
        } else if (r + 2 == AGG_ROWS) {
            asm volatile("cp.async.wait_group 1;");
        } else {
            asm volatile("cp.async.wait_group 0;");
        }
        __syncthreads();
        float wv = ws[s][j];
#pragma unroll
        for (int t = 0; t < 64; t++) acc[t] += wv * __half2float(vs[s][sb + 8 * t]);
        __syncthreads();
    }
    float* p = part + (size_t)blk * (Kslots * Ss) + j * Ss;
#pragma unroll
    for (int t = 0; t < 64; t++) p[sb + 8 * t] = acc[t];
}

__global__ void finalize_kernel(const float* __restrict__ state, float* __restrict__ out) {
    int e = blockIdx.x * blockDim.x + threadIdx.x;
    if (e >= Kslots * Ss) return;
    float se = 0.f, sw = 0.f;
    for (int r = 0; r < AGG_BLOCKS; r++) {
        se += g_partE[(size_t)r * (Kslots * Ss) + e];
        sw += g_partW[(size_t)r * (Kslots * Ss) + e];
    }
    float ea = fminf(fmaxf(se, 0.f), 1.f);
    out[e] = state[e] * (1.f - ea) + sw;
}

// ======================= launcher ============================================
extern "C" void kernel_launch(void* const* d_in, const int* in_sizes, int n_in,
                              void* d_out, int out_size) {
    const float* nf    = (const float*)d_in[0];
    const float* state = (const float*)d_in[1];
    const float* Wq    = (const float*)d_in[2];
    const float* Wk    = (const float*)d_in[3];
    const float* Wv    = (const float*)d_in[4];
    const float* Wo    = (const float*)d_in[5];
    const float* gam   = (const float*)d_in[6];
    const float* bet   = (const float*)d_in[7];
    const float* Wa    = (const float*)d_in[8];
    const float* Wg    = (const float*)d_in[9];
    const float* bg    = (const float*)d_in[10];
    const float* We    = (const float*)d_in[11];
    const float* be    = (const float*)d_in[12];
    const float* Wc    = (const float*)d_in[13];
    const float* bc    = (const float*)d_in[14];

    float* h_out  = (float*)d_out;
    float* ns_out = (float*)d_out + (size_t)Nn * Dd;

    auto sym = [](const void* s) {
        void* p = nullptr;
        cudaGetSymbolAddress(&p, s);
        return p;
    };
    __half* ath  = (__half*)sym(g_ath);
    __half* hh   = (__half*)sym(g_hh);
    __half* roh  = (__half*)sym(g_roh);
    __half* ersh = (__half*)sym(g_ersh);
    __half* cnth = (__half*)sym(g_cnth);
    float* wtd   = (float*)sym(g_weighted);
    float* gate  = (float*)sym(g_gate);
    float* pE    = (float*)sym(g_partE);
    float* pW    = (float*)sym(g_partW);
    __half* m1T  = (__half*)sym(g_m1T);
    __half* m2T  = (__half*)sym(g_m2T);
    __half* vwoT = (__half*)sym(g_vwoT);
    __half* wall = (__half*)sym(g_wall);
    float* Kp32  = (float*)sym(g_Kp32);
    float* V32   = (float*)sym(g_V32);
    float* WoT32 = (float*)sym(g_WoT32);
    const size_t SD = (size_t)Ss * Dd;

    const int SM_N64S  = 3 * ((64 + 64) * 128);    // 49152 (BM=64 small GEMMs)
    const int SM_N128  = 3 * ((128 + 128) * 128);  // 98304
    cudaFuncSetAttribute(hgemm<64, 64, 7, 1, true>,    cudaFuncAttributeMaxDynamicSharedMemorySize, SM_N64S);
    cudaFuncSetAttribute(hgemm<64, 64, 7, 2, false>,   cudaFuncAttributeMaxDynamicSharedMemorySize, SM_N64S);
    cudaFuncSetAttribute(hgemm<128, 128, 8, 0, false>, cudaFuncAttributeMaxDynamicSharedMemorySize, SM_N128);
    cudaFuncSetAttribute(hgemm<128, 128, 6, 0, false>, cudaFuncAttributeMaxDynamicSharedMemorySize, SM_N128);

    const float scale = 0.044194173824159216f;  // 1/sqrt(512)
    const int FOLD_BLKS = (Kslots * Dd * 32) / 256;  // 8192

    // ---- prep (launch slot 4 = logits GEMM, targeted for ncu) ----
    kv2_kernel<<<Kslots, 512>>>(state, Wk, Wv);                       // 1
    fold_kernel<true><<<FOLD_BLKS, 256>>>(Wq, Kp32, m1T, scale);      // 2
    fold_kernel<true><<<FOLD_BLKS, 256>>>(Wa, state, m2T, 1.0f);      // 3
    hgemm<64, 64, 7, 1, true><<<dim3(1, 1024), 256, SM_N64S>>>(       // 4 (profiled)
        nullptr, nf, m1T, Dd, 64,
        nullptr, ath, nullptr, nullptr, nullptr, nullptr);
    transpose_f_kernel<<<dim3(Dd / 32, Ss / 32), dim3(32, 8)>>>(Wo, WoT32, Ss, Dd);
    fold_kernel<false><<<FOLD_BLKS, 256>>>(WoT32, V32, vwoT, 1.0f);
    transpose_h_kernel<<<dim3(Ss / 32, Dd / 32), dim3(32, 8)>>>(We, wall, Dd, Ss);
    transpose_h_kernel<<<dim3(Ss / 32, Dd / 32), dim3(32, 8)>>>(Wc, wall + SD, Dd, Ss);

    // ---- read path ----
    hgemm<128, 128, 8, 0, false><<<dim3(8, 512), 256, SM_N128>>>(
        ath, nullptr, vwoT, 64, Dd,
        nullptr, roh, nullptr, nullptr, nullptr, nullptr);
    ln_gate_kernel<<<Nn, 256>>>(nf, roh, gam, bet, Wg, bg, h_out, hh, gate);

    // ---- write path ----
    hgemm<64, 64, 7, 2, false><<<dim3(1, 1024), 256, SM_N64S>>>(
        hh, nullptr, m2T, Dd, 64,
        wtd, nullptr, nullptr, nullptr, nullptr, gate);
    hgemm<128, 128, 6, 0, false><<<dim3(8, 512), 256, SM_N128>>>(
        hh, nullptr, wall, Dd, 2 * Ss,
        nullptr, ersh, cnth, be, bc, nullptr);
    aggregate_kernel<<<AGG_BLOCKS, 512>>>(wtd, ersh, pE);
    aggregate_kernel<<<AGG_BLOCKS, 512>>>(wtd, cnth, pW);
    finalize_kernel<<<(Kslots * Ss + 255) / 256, 256>>>(state, ns_out);
}

// round 17
// speedup vs baseline: 1.2190x; 1.2190x over previous
#include <cuda_runtime.h>
#include <cuda_fp16.h>
#include <math.h>
#include <stdint.h>

#define Nn 65536
#define Dd 1024
#define Ss 512
#define Kslots 64
#define AGG_BLOCKS 256
#define AGG_ROWS (Nn / AGG_BLOCKS)

// ======================= helpers =============================================
__device__ __forceinline__ uint32_t smem_u32(const void* p) {
    uint32_t a;
    asm("{ .reg .u64 t; cvta.to.shared.u64 t, %1; cvt.u32.u64 %0, t; }" : "=r"(a) : "l"(p));
    return a;
}
__device__ __forceinline__ void cp16(uint32_t dst, const void* src) {
    asm volatile("cp.async.cg.shared.global [%0], [%1], 16;" :: "r"(dst), "l"(src));
}
__device__ __forceinline__ void ldsm4(uint32_t* r, uint32_t addr) {
    asm volatile("ldmatrix.sync.aligned.m8n8.x4.shared.b16 {%0,%1,%2,%3}, [%4];"
                 : "=r"(r[0]), "=r"(r[1]), "=r"(r[2]), "=r"(r[3]) : "r"(addr));
}
__device__ __forceinline__ void hmma16(float* c, const uint32_t* a, const uint32_t* b) {
    asm volatile(
        "mma.sync.aligned.m16n8k16.row.col.f32.f16.f16.f32 "
        "{%0,%1,%2,%3}, {%4,%5,%6,%7}, {%8,%9}, {%0,%1,%2,%3};"
        : "+f"(c[0]), "+f"(c[1]), "+f"(c[2]), "+f"(c[3])
        : "r"(a[0]), "r"(a[1]), "r"(a[2]), "r"(a[3]), "r"(b[0]), "r"(b[1]));
}

// ======================= device global scratch ===============================
__device__ __align__(1024) __half g_ath[(size_t)Nn * Kslots];
__device__ __align__(1024) __half g_hh[(size_t)Nn * Dd];
__device__ __align__(1024) __half g_roh[(size_t)Nn * Dd];
__device__ __align__(1024) __half g_ersh[(size_t)Nn * Ss];
__device__ __align__(1024) __half g_cnth[(size_t)Nn * Ss];
__device__ __align__(1024) float g_weighted[(size_t)Nn * Kslots];
__device__ float g_gate[Nn];
__device__ __align__(1024) float g_partE[(size_t)AGG_BLOCKS * Kslots * Ss];
__device__ __align__(1024) float g_partW[(size_t)AGG_BLOCKS * Kslots * Ss];
// folded small matrices (fp16, hgemm-B layout [rows][K] K-major)
__device__ __align__(1024) __half g_m1T[(size_t)Kslots * Dd];
__device__ __align__(1024) __half g_m2T[(size_t)Kslots * Dd];
__device__ __align__(1024) __half g_vwoT[(size_t)Dd * Kslots];
__device__ __align__(1024) __half g_wall[(size_t)(2 * Ss) * Dd];
// fp32 precompute intermediates
__device__ __align__(1024) float g_Kp32[Kslots * Ss];
__device__ __align__(1024) float g_V32[Kslots * Ss];
__device__ __align__(1024) float g_WoT32[(size_t)Dd * Ss];

// ======================= fp16 GEMM (mma.sync, 3-stage pipeline) ==============
// C[M,Nc] = act( A @ B^T );  A [M,Kd] (fp16, or fp32 if A32), B [Nc,Kd] fp16.
// MODE 6: Nc=1024 fused: [0,512) sigmoid+bias -> Chi, [512,1024) tanh+bias2 -> Clo (fp16).
// MODE 7: Nc=64, fused row-softmax. SOFT=1: fp16 attn -> Chi. SOFT=2: fp32 softmax*gate -> Cf.
// MODE 8: fp16 out -> Chi.
template <int BM, int BN, int MODE, int SOFT, bool A32>
__global__ void __launch_bounds__(256, 2)
hgemm(const __half* __restrict__ Ah,
      const float* __restrict__ Af,
      const __half* __restrict__ B,
      int Kd, int Nc,
      float* __restrict__ Cf,
      __half* __restrict__ Chi, __half* __restrict__ Clo,
      const float* __restrict__ bias, const float* __restrict__ bias2,
      const float* __restrict__ gatep)
{
    constexpr int NWN = (BN >= 128) ? 4 : 2;
    constexpr int NWM = 8 / NWN;
    constexpr int WM = BM / NWM;
    constexpr int MF = WM / 16;
    constexpr int NF = (BN / NWN) / 8;
    constexpr int APL = BM * 128;
    constexpr int BPL = BN * 128;
    constexpr int STAGE = APL + BPL;
    constexpr int SEGS = (BM + BN) * 8;
    constexpr int SPT = SEGS / 256;
    constexpr int SPT_A = (BM * 8) / 256;
    constexpr int SPT_B = (BN * 8) / 256;

    extern __shared__ char smem_raw[];
    uint32_t sb0 = smem_u32(smem_raw);

    int tid = threadIdx.x, w = tid >> 5, lane = tid & 31;
    int row0 = blockIdx.y * BM, col0 = blockIdx.x * BN;
    int wm0 = (w / NWN) * WM, wn0 = (w % NWN) * (BN / NWN);
    int nch = Kd >> 6;

    float acc[MF][NF][4];
#pragma unroll
    for (int i = 0; i < MF; i++)
#pragma unroll
        for (int j = 0; j < NF; j++)
#pragma unroll
            for (int u = 0; u < 4; u++) acc[i][j][u] = 0.f;

    auto issue = [&](int c) {
        uint32_t sbase = sb0 + (c % 3) * STAGE;
        int k0 = c << 6;
        if (A32) {
#pragma unroll
            for (int i = 0; i < SPT_A; i++) {
                int sg = i * 256 + tid;
                int lr = sg >> 3, q = sg & 7;
                const float4* src = reinterpret_cast<const float4*>(
                    Af + (size_t)(row0 + lr) * Kd + k0 + q * 8);
                float4 v0 = src[0], v1 = src[1];
                __half2 h0 = __floats2half2_rn(v0.x, v0.y);
                __half2 h1 = __floats2half2_rn(v0.z, v0.w);
                __half2 h2 = __floats2half2_rn(v1.x, v1.y);
                __half2 h3 = __floats2half2_rn(v1.z, v1.w);
                uint32_t off = (uint32_t)(lr * 128 + q * 16);
                off ^= (off >> 3) & 0x70;
                uint4 pk;
                pk.x = *reinterpret_cast<uint32_t*>(&h0);
                pk.y = *reinterpret_cast<uint32_t*>(&h1);
                pk.z = *reinterpret_cast<uint32_t*>(&h2);
                pk.w = *reinterpret_cast<uint32_t*>(&h3);
                *reinterpret_cast<uint4*>(smem_raw + ((c % 3) * STAGE + off)) = pk;
            }
#pragma unroll
            for (int i = 0; i < SPT_B; i++) {
                int sg = i * 256 + tid;
                int lr = sg >> 3, q = sg & 7;
                const __half* srcp = B + (size_t)(col0 + lr) * Kd + k0 + q * 8;
                uint32_t off = (uint32_t)(lr * 128 + q * 16);
                off ^= (off >> 3) & 0x70;
                cp16(sbase + APL + off, (const void*)srcp);
            }
        } else {
#pragma unroll
            for (int i = 0; i < SPT; i++) {
                int sg = i * 256 + tid;
                int rr = sg >> 3, q = sg & 7;
                const __half* srcp;
                uint32_t dstb;
                int lr;
                if (rr < BM) {
                    lr = rr;
                    srcp = Ah + (size_t)(row0 + lr) * Kd + k0 + q * 8;
                    dstb = sbase;
                } else {
                    lr = rr - BM;
                    srcp = B + (size_t)(col0 + lr) * Kd + k0 + q * 8;
                    dstb = sbase + APL;
                }
                uint32_t off = (uint32_t)(lr * 128 + q * 16);
                off ^= (off >> 3) & 0x70;
                cp16(dstb + off, (const void*)srcp);
            }
        }
        asm volatile("cp.async.commit_group;");
    };

    issue(0);
    if (nch > 1) issue(1);
    for (int c = 0; c < nch; c++) {
        if (c + 2 < nch) {
            issue(c + 2);
            asm volatile("cp.async.wait_group 2;");
        } else if (c + 1 < nch) {
            asm volatile("cp.async.wait_group 1;");
        } else {
            asm volatile("cp.async.wait_group 0;");
        }
        __syncthreads();

        uint32_t sA = sb0 + (c % 3) * STAGE;
        uint32_t sB = sA + APL;
#pragma unroll
        for (int ks = 0; ks < 4; ks++) {
            uint32_t ah[MF][4];
#pragma unroll
            for (int i = 0; i < MF; i++) {
                uint32_t off = (uint32_t)((wm0 + i * 16 + (lane & 15)) * 128 +
                                          ks * 32 + ((lane >> 4) << 4));
                off ^= (off >> 3) & 0x70;
                ldsm4(ah[i], sA + off);
            }
            uint32_t b[NF][2];
#pragma unroll
            for (int j2 = 0; j2 < NF / 2; j2++) {
                uint32_t off = (uint32_t)((wn0 + j2 * 16 + (lane & 7) + ((lane >> 4) << 3)) * 128 +
                                          ks * 32 + (((lane >> 3) & 1) << 4));
                off ^= (off >> 3) & 0x70;
                uint32_t t[4];
                ldsm4(t, sB + off);
                b[2 * j2][0] = t[0]; b[2 * j2][1] = t[1];
                b[2 * j2 + 1][0] = t[2]; b[2 * j2 + 1][1] = t[3];
            }
#pragma unroll
            for (int i = 0; i < MF; i++)
#pragma unroll
                for (int j = 0; j < NF; j++) hmma16(acc[i][j], ah[i], b[j]);
        }
        __syncthreads();
    }

    // ---- epilogue ----
    if (MODE == 7) {
        float* Sf = reinterpret_cast<float*>(smem_raw);
#pragma unroll
        for (int i = 0; i < MF; i++)
#pragma unroll
            for (int j = 0; j < NF; j++) {
                int rl = wm0 + i * 16 + (lane >> 2);
                int cl = wn0 + j * 8 + ((lane & 3) << 1);
#pragma unroll
                for (int half = 0; half < 2; half++) {
                    Sf[(rl + half * 8) * 68 + cl]     = acc[i][j][half * 2 + 0];
                    Sf[(rl + half * 8) * 68 + cl + 1] = acc[i][j][half * 2 + 1];
                }
            }
        __syncthreads();
#pragma unroll 1
        for (int r2 = 0; r2 < 16; r2++) {
            int rl = w * 16 + r2;
            float v0 = Sf[rl * 68 + lane];
            float v1 = Sf[rl * 68 + 32 + lane];
            float m = fmaxf(v0, v1);
#pragma unroll
            for (int o = 16; o; o >>= 1) m = fmaxf(m, __shfl_xor_sync(0xffffffffu, m, o));
            float e0 = __expf(v0 - m), e1 = __expf(v1 - m);
            float s = e0 + e1;
#pragma unroll
            for (int o = 16; o; o >>= 1) s += __shfl_xor_sync(0xffffffffu, s, o);
            float inv = 1.f / s;
            size_t grow = (size_t)(row0 + rl);
            if (SOFT == 2) inv *= gatep[grow];
            float a0 = e0 * inv, a1 = e1 * inv;
            if (SOFT == 1) {
                Chi[grow * 64 + lane] = __float2half(a0);
                Chi[grow * 64 + 32 + lane] = __float2half(a1);
            } else {
                Cf[grow * 64 + lane] = a0;
                Cf[grow * 64 + 32 + lane] = a1;
            }
        }
        return;
    }

    int seg = col0 >> 9;   // MODE 6
#pragma unroll
    for (int i = 0; i < MF; i++) {
#pragma unroll
        for (int j = 0; j < NF; j++) {
            int r = row0 + wm0 + i * 16 + (lane >> 2);
            int cp = col0 + wn0 + j * 8 + ((lane & 3) << 1);
#pragma unroll
            for (int half = 0; half < 2; half++) {
                int rr = r + half * 8;
                float x0 = acc[i][j][half * 2 + 0];
                float x1 = acc[i][j][half * 2 + 1];
                if (MODE == 6) {
                    int colL = cp - seg * 512;
                    __half2 o;
                    if (seg == 0) {
                        o.x = __float2half(1.f / (1.f + __expf(-(x0 + bias[colL]))));
                        o.y = __float2half(1.f / (1.f + __expf(-(x1 + bias[colL + 1]))));
                        *reinterpret_cast<__half2*>(&Chi[(size_t)rr * Ss + colL]) = o;
                    } else {
                        o.x = __float2half(tanhf(x0 + bias2[colL]));
                        o.y = __float2half(tanhf(x1 + bias2[colL + 1]));
                        *reinterpret_cast<__half2*>(&Clo[(size_t)rr * Ss + colL]) = o;
                    }
                } else {  // MODE 8
                    __half2 o;
                    o.x = __float2half(x0);
                    o.y = __float2half(x1);
                    *reinterpret_cast<__half2*>(&Chi[(size_t)rr * Nc + cp]) = o;
                }
            }
        }
    }
}

// ======================= prep / elementwise kernels ==========================
__global__ void transpose_h_kernel(const float* __restrict__ W,
                                   __half* __restrict__ T, int R, int C) {
    __shared__ float t[32][33];
    int c0 = blockIdx.x * 32, r0 = blockIdx.y * 32;
    int tx = threadIdx.x, ty = threadIdx.y;
#pragma unroll
    for (int i = 0; i < 32; i += 8)
        t[ty + i][tx] = W[(size_t)(r0 + ty + i) * C + c0 + tx];
    __syncthreads();
#pragma unroll
    for (int i = 0; i < 32; i += 8)
        T[(size_t)(c0 + ty + i) * R + r0 + tx] = __float2half(t[tx][ty + i]);
}

__global__ void transpose_f_kernel(const float* __restrict__ W,
                                   float* __restrict__ T, int R, int C) {
    __shared__ float t[32][33];
    int c0 = blockIdx.x * 32, r0 = blockIdx.y * 32;
    int tx = threadIdx.x, ty = threadIdx.y;
#pragma unroll
    for (int i = 0; i < 32; i += 8)
        t[ty + i][tx] = W[(size_t)(r0 + ty + i) * C + c0 + tx];
    __syncthreads();
#pragma unroll
    for (int i = 0; i < 32; i += 8)
        T[(size_t)(c0 + ty + i) * R + r0 + tx] = t[tx][ty + i];
}

__global__ void __launch_bounds__(512)
kv2_kernel(const float* __restrict__ state,
           const float* __restrict__ Wk,
           const float* __restrict__ Wv) {
    int j = blockIdx.x;
    int c = threadIdx.x;
    __shared__ float srow[Ss];
    srow[c] = state[j * Ss + c];
    __syncthreads();
    float ak = 0.f, av = 0.f;
#pragma unroll 8
    for (int t = 0; t < Ss; t++) {
        float s = srow[t];
        ak += s * Wk[t * Ss + c];
        av += s * Wv[t * Ss + c];
    }
    g_Kp32[j * Ss + c] = ak;
    g_V32[j * Ss + c] = av;
}

template <bool JD>
__global__ void __launch_bounds__(256)
fold_kernel(const float* __restrict__ A, const float* __restrict__ B,
            __half* __restrict__ out, float scale) {
    int w = (blockIdx.x * 256 + threadIdx.x) >> 5;
    int lane = threadIdx.x & 31;
    int j = w & 63, d = w >> 6;
    const float* ar = A + (size_t)d * Ss;
    const float* br = B + (size_t)j * Ss;
    float acc = 0.f;
#pragma unroll
    for (int i = 0; i < 16; i++)
        acc += ar[lane + 32 * i] * br[lane + 32 * i];
#pragma unroll
    for (int o = 16; o; o >>= 1) acc += __shfl_xor_sync(0xffffffffu, acc, o);
    if (lane == 0) {
        size_t idx = JD ? (size_t)j * Dd + d : (size_t)d * 64 + j;
        out[idx] = __float2half(acc * scale);
    }
}

__global__ void ln_gate_kernel(const float* __restrict__ nf,
                               const __half* __restrict__ roh,
                               const float* __restrict__ gamma,
                               const float* __restrict__ beta,
                               const float* __restrict__ Wg,
                               const float* __restrict__ bg,
                               float* __restrict__ h,
                               __half* __restrict__ hh,
                               float* __restrict__ gate) {
    int row = blockIdx.x;
    int tid = threadIdx.x;
    __shared__ float sh[16];
    float4 a = reinterpret_cast<const float4*>(nf + (size_t)row * Dd)[tid];
    __half2 r0 = reinterpret_cast<const __half2*>(roh + (size_t)row * Dd)[tid * 2];
    __half2 r1 = reinterpret_cast<const __half2*>(roh + (size_t)row * Dd)[tid * 2 + 1];
    float v0 = a.x + __half2float(r0.x), v1 = a.y + __half2float(r0.y);
    float v2 = a.z + __half2float(r1.x), v3 = a.w + __half2float(r1.y);
    float s = v0 + v1 + v2 + v3;
    float sq = v0 * v0 + v1 * v1 + v2 * v2 + v3 * v3;
    int lane = tid & 31, wid = tid >> 5;
#pragma unroll
    for (int o = 16; o; o >>= 1) {
        s += __shfl_xor_sync(0xffffffffu, s, o);
        sq += __shfl_xor_sync(0xffffffffu, sq, o);
    }
    if (lane == 0) { sh[wid] = s; sh[8 + wid] = sq; }
    __syncthreads();
    if (tid < 32) {
        float rs = (lane < 8) ? sh[lane] : 0.f;
        float rq = (lane < 8) ? sh[8 + lane] : 0.f;
#pragma unroll
        for (int o = 4; o; o >>= 1) {
            rs += __shfl_xor_sync(0xffffffffu, rs, o);
            rq += __shfl_xor_sync(0xffffffffu, rq, o);
        }
        if (lane == 0) { sh[0] = rs; sh[1] = rq; }
    }
    __syncthreads();
    float mu = sh[0] * (1.f / Dd);
    float var = sh[1] * (1.f / Dd) - mu * mu;
    float inv = rsqrtf(var + 1e-6f);
    __syncthreads();

    float4 g4 = reinterpret_cast<const float4*>(gamma)[tid];
    float4 b4 = reinterpret_cast<const float4*>(beta)[tid];
    float h0 = (v0 - mu) * inv * g4.x + b4.x;
    float h1 = (v1 - mu) * inv * g4.y + b4.y;
    float h2 = (v2 - mu) * inv * g4.z + b4.z;
    float h3 = (v3 - mu) * inv * g4.w + b4.w;
    float4 o4; o4.x = h0; o4.y = h1; o4.z = h2; o4.w = h3;
    reinterpret_cast<float4*>(h + (size_t)row * Dd)[tid] = o4;

    __half2 p0, p1;
    p0.x = __float2half(h0); p0.y = __float2half(h1);
    p1.x = __float2half(h2); p1.y = __float2half(h3);
    reinterpret_cast<__half2*>(hh + (size_t)row * Dd)[tid * 2] = p0;
    reinterpret_cast<__half2*>(hh + (size_t)row * Dd)[tid * 2 + 1] = p1;

    float4 w4 = reinterpret_cast<const float4*>(Wg)[tid];
    float gd = h0 * w4.x + h1 * w4.y + h2 * w4.z + h3 * w4.w;
#pragma unroll
    for (int o = 16; o; o >>= 1) gd += __shfl_xor_sync(0xffffffffu, gd, o);
    if (lane == 0) sh[wid] = gd;
    __syncthreads();
    if (tid == 0) {
        float t = 0.f;
#pragma unroll
        for (int wv = 0; wv < 8; wv++) t += sh[wv];
        gate[row] = 1.f / (1.f + __expf(-(t + bg[0])));
    }
}

// aggregate with cp.async double-buffered row prefetch (R14-proven):
// part[blk] = sum_{rows in chunk} w[row]^T (outer) vec[row]
__global__ void __launch_bounds__(512)
aggregate_kernel(const float* __restrict__ w, const __half* __restrict__ vec,
                 float* __restrict__ part) {
    int blk = blockIdx.x;
    int tid = threadIdx.x;
    int j = tid >> 3;
    int sb = tid & 7;
    float acc[64];
#pragma unroll
    for (int t = 0; t < 64; t++) acc[t] = 0.f;
    __shared__ __align__(16) float ws[2][64];
    __shared__ __align__(16) __half vs[2][Ss];
    uint32_t ws0 = smem_u32(&ws[0][0]);
    uint32_t ws1 = smem_u32(&ws[1][0]);
    uint32_t vs0 = smem_u32(&vs[0][0]);
    uint32_t vs1 = smem_u32(&vs[1][0]);
    int r0 = blk * AGG_ROWS;

    auto issue = [&](int r, int s) {
        size_t row = (size_t)(r0 + r);
        if (tid < 16) {
            cp16((s ? ws1 : ws0) + tid * 16, (const void*)(w + row * 64 + tid * 4));
        } else if (tid < 80) {
            int seg = tid - 16;
            cp16((s ? vs1 : vs0) + seg * 16, (const void*)(vec + row * Ss + seg * 8));
        }
        asm volatile("cp.async.commit_group;");
    };

    issue(0, 0);
    for (int r = 0; r < AGG_ROWS; r++) {
        int s = r & 1;
        if (r + 1 < AGG_ROWS) {
            issue(r + 1, s ^ 1);
            asm volatile("cp.async.wait_group 1;");
        } else {
            asm volatile("cp.async.wait_group 0;");
        }
        __syncthreads();
        float wv = ws[s][j];
#pragma unroll
        for (int t = 0; t < 64; t++) acc[t] += wv * __half2float(vs[s][sb + 8 * t]);
        __syncthreads();
    }
    float* p = part + (size_t)blk * (Kslots * Ss) + j * Ss;
#pragma unroll
    for (int t = 0; t < 64; t++) p[sb + 8 * t] = acc[t];
}

__global__ void finalize_kernel(const float* __restrict__ state, float* __restrict__ out) {
    int e = blockIdx.x * blockDim.x + threadIdx.x;
    if (e >= Kslots * Ss) return;
    float se = 0.f, sw = 0.f;
#pragma unroll 8
    for (int r = 0; r < AGG_BLOCKS; r++) {
        se += g_partE[(size_t)r * (Kslots * Ss) + e];
        sw += g_partW[(size_t)r * (Kslots * Ss) + e];
    }
    float ea = fminf(fmaxf(se, 0.f), 1.f);
    out[e] = state[e] * (1.f - ea) + sw;
}

// ======================= launcher ============================================
extern "C" void kernel_launch(void* const* d_in, const int* in_sizes, int n_in,
                              void* d_out, int out_size) {
    const float* nf    = (const float*)d_in[0];
    const float* state = (const float*)d_in[1];
    const float* Wq    = (const float*)d_in[2];
    const float* Wk    = (const float*)d_in[3];
    const float* Wv    = (const float*)d_in[4];
    const float* Wo    = (const float*)d_in[5];
    const float* gam   = (const float*)d_in[6];
    const float* bet   = (const float*)d_in[7];
    const float* Wa    = (const float*)d_in[8];
    const float* Wg    = (const float*)d_in[9];
    const float* bg    = (const float*)d_in[10];
    const float* We    = (const float*)d_in[11];
    const float* be    = (const float*)d_in[12];
    const float* Wc    = (const float*)d_in[13];
    const float* bc    = (const float*)d_in[14];

    float* h_out  = (float*)d_out;
    float* ns_out = (float*)d_out + (size_t)Nn * Dd;

    auto sym = [](const void* s) {
        void* p = nullptr;
        cudaGetSymbolAddress(&p, s);
        return p;
    };
    __half* ath  = (__half*)sym(g_ath);
    __half* hh   = (__half*)sym(g_hh);
    __half* roh  = (__half*)sym(g_roh);
    __half* ersh = (__half*)sym(g_ersh);
    __half* cnth = (__half*)sym(g_cnth);
    float* wtd   = (float*)sym(g_weighted);
    float* gate  = (float*)sym(g_gate);
    float* pE    = (float*)sym(g_partE);
    float* pW    = (float*)sym(g_partW);
    __half* m1T  = (__half*)sym(g_m1T);
    __half* m2T  = (__half*)sym(g_m2T);
    __half* vwoT = (__half*)sym(g_vwoT);
    __half* wall = (__half*)sym(g_wall);
    float* Kp32  = (float*)sym(g_Kp32);
    float* V32   = (float*)sym(g_V32);
    float* WoT32 = (float*)sym(g_WoT32);
    const size_t SD = (size_t)Ss * Dd;

    const int SM_N64  = 3 * ((128 + 64) * 128);    // 73728
    const int SM_N128 = 3 * ((128 + 128) * 128);   // 98304
    cudaFuncSetAttribute(hgemm<128, 64, 7, 1, true>,   cudaFuncAttributeMaxDynamicSharedMemorySize, SM_N64);
    cudaFuncSetAttribute(hgemm<128, 64, 7, 2, false>,  cudaFuncAttributeMaxDynamicSharedMemorySize, SM_N64);
    cudaFuncSetAttribute(hgemm<128, 128, 8, 0, false>, cudaFuncAttributeMaxDynamicSharedMemorySize, SM_N128);
    cudaFuncSetAttribute(hgemm<128, 128, 6, 0, false>, cudaFuncAttributeMaxDynamicSharedMemorySize, SM_N128);

    const float scale = 0.044194173824159216f;  // 1/sqrt(512)
    const int FOLD_BLKS = (Kslots * Dd * 32) / 256;  // 8192

    // ---- prep (launch slot 4 = logits GEMM, targeted for ncu) ----
    kv2_kernel<<<Kslots, 512>>>(state, Wk, Wv);                       // 1
    fold_kernel<true><<<FOLD_BLKS, 256>>>(Wq, Kp32, m1T, scale);      // 2
    fold_kernel<true><<<FOLD_BLKS, 256>>>(Wa, state, m2T, 1.0f);      // 3
    hgemm<128, 64, 7, 1, true><<<dim3(1, 512), 256, SM_N64>>>(        // 4 (profiled)
        nullptr, nf, m1T, Dd, 64,
        nullptr, ath, nullptr, nullptr, nullptr, nullptr);
    transpose_f_kernel<<<dim3(Dd / 32, Ss / 32), dim3(32, 8)>>>(Wo, WoT32, Ss, Dd);
    fold_kernel<false><<<FOLD_BLKS, 256>>>(WoT32, V32, vwoT, 1.0f);
    transpose_h_kernel<<<dim3(Ss / 32, Dd / 32), dim3(32, 8)>>>(We, wall, Dd, Ss);
    transpose_h_kernel<<<dim3(Ss / 32, Dd / 32), dim3(32, 8)>>>(Wc, wall + SD, Dd, Ss);

    // ---- read path ----
    hgemm<128, 128, 8, 0, false><<<dim3(8, 512), 256, SM_N128>>>(
        ath, nullptr, vwoT, 64, Dd,
        nullptr, roh, nullptr, nullptr, nullptr, nullptr);
    ln_gate_kernel<<<Nn, 256>>>(nf, roh, gam, bet, Wg, bg, h_out, hh, gate);

    // ---- write path ----
    hgemm<128, 64, 7, 2, false><<<dim3(1, 512), 256, SM_N64>>>(
        hh, nullptr, m2T, Dd, 64,
        wtd, nullptr, nullptr, nullptr, nullptr, gate);
    hgemm<128, 128, 6, 0, false><<<dim3(8, 512), 256, SM_N128>>>(
        hh, nullptr, wall, Dd, 2 * Ss,
        nullptr, ersh, cnth, be, bc, nullptr);
    aggregate_kernel<<<AGG_BLOCKS, 512>>>(wtd, ersh, pE);
    aggregate_kernel<<<AGG_BLOCKS, 512>>>(wtd, cnth, pW);
    finalize_kernel<<<(Kslots * Ss + 255) / 256, 256>>>(state, ns_out);
}